// round 6
// baseline (speedup 1.0000x reference)
#include <cuda_runtime.h>
#include <cstdint>

// FuseSliceCatSameInputModule_v2: gather 8 groups of 8 disjoint 32-wide column
// slices from input [rows, 4096] fp32 into 8 outputs [rows, 256], packed
// group-major into d_out.
//
// out[g][row][c] (c in [0,256)) = in[row][g*512 + (c/32)*64 + (c%32)]
//
// Every 32-float slice is one aligned 128B line. float4-vectorized:
// input float4 col = g*128 + (c4>>3)*16 + (c4&7), c4 in [0,64).
//
// Persistent one-wave kernel: grid (152, 1, 8) = 1216 blocks = 152 SMs x 8
// resident CTAs (launch_bounds caps regs so all fit). Each block grid-strides
// over its group's row-tiles (16 rows/tile; 256 threads x 4 float4, loads
// batched ahead of stores, streaming cache hints). No wave transitions.

static constexpr int IN_COLS4     = 4096 / 4;  // 1024
static constexpr int OUT_COLS4    = 256 / 4;   // 64
static constexpr int ROWS_PER_BLK = 16;
static constexpr int NSM          = 152;       // GB300 SM count

__global__ __launch_bounds__(256, 8)
void slice_cat_kernel(const float4* __restrict__ in, float4* __restrict__ out,
                      int rows)
{
    const int t    = threadIdx.x;
    const int c4   = t & 63;
    const int rsub = t >> 6;                 // 0..3
    const int g    = blockIdx.z;

    const int j = c4 >> 3;
    const int w = c4 & 7;

    const int  in_col4  = (g << 7) + (j << 4) + w;      // g*128 + j*16 + w
    const long out_base = ((long)g * rows) * OUT_COLS4 + c4;

    const int ntiles = (rows + ROWS_PER_BLK - 1) / ROWS_PER_BLK;

    for (int tile = blockIdx.x; tile < ntiles; tile += gridDim.x) {
        const int row0 = tile * ROWS_PER_BLK + rsub;

        const float4* ip = in  + (long)row0 * IN_COLS4 + in_col4;
        float4*       op = out + out_base + (long)row0 * OUT_COLS4;

        if (row0 + 12 < rows) {
            // fast path: 4 independent loads issued before any store
            float4 v0 = __ldcs(ip);
            float4 v1 = __ldcs(ip + 4L * IN_COLS4);
            float4 v2 = __ldcs(ip + 8L * IN_COLS4);
            float4 v3 = __ldcs(ip + 12L * IN_COLS4);
            __stcs(op,                   v0);
            __stcs(op + 4L * OUT_COLS4,  v1);
            __stcs(op + 8L * OUT_COLS4,  v2);
            __stcs(op + 12L * OUT_COLS4, v3);
        } else {
#pragma unroll
            for (int k = 0; k < 4; ++k) {
                const int row = row0 + (k << 2);
                if (row < rows)
                    __stcs(op + (long)(k << 2) * OUT_COLS4,
                           __ldcs(ip + (long)(k << 2) * IN_COLS4));
            }
        }
    }
}

extern "C" void kernel_launch(void* const* d_in, const int* in_sizes, int n_in,
                              void* d_out, int out_size)
{
    const float4* in  = (const float4*)d_in[0];
    float4*       out = (float4*)d_out;

    const int rows = in_sizes[0] / 4096;     // 16384 reference

    dim3 block(256, 1, 1);
    dim3 grid(NSM, 1, 8);                    // one resident wave: 152 x 8 CTAs
    slice_cat_kernel<<<grid, block>>>(in, out, rows);
}

// round 12
// speedup vs baseline: 1.0516x; 1.0516x over previous
#include <cuda_runtime.h>
#include <cstdint>

// FuseSliceCatSameInputModule_v2: gather 8 groups of 8 disjoint 32-wide column
// slices from input [rows, 4096] fp32 into 8 outputs [rows, 256], packed
// group-major into d_out.
//
// out[g][row][c] (c in [0,256)) = in[row][g*512 + (c/32)*64 + (c%32)]
//
// Every 32-float slice is one aligned 128B line. float4-vectorized:
// input float4 col = g*128 + (c4>>3)*16 + (c4&7), c4 in [0,64).
//
// Flat grid (512,1,8). Each block: 32 rows of one group; 256 threads x
// 8 float4. All 8 independent loads issued before any store (MLP=8, long
// read burst, then long write burst). Streaming cache hints on both sides.

static constexpr int IN_COLS4     = 4096 / 4;  // 1024
static constexpr int OUT_COLS4    = 256 / 4;   // 64
static constexpr int ROWS_PER_BLK = 32;        // 256 thr * 8 f4 / 64 f4-per-row

__global__ __launch_bounds__(256)
void slice_cat_kernel(const float4* __restrict__ in, float4* __restrict__ out,
                      int rows)
{
    const int t    = threadIdx.x;
    const int c4   = t & 63;
    const int rsub = t >> 6;                 // 0..3
    const int g    = blockIdx.z;
    const int row0 = blockIdx.x * ROWS_PER_BLK + rsub;

    const int j = c4 >> 3;
    const int w = c4 & 7;

    const int  in_col4  = (g << 7) + (j << 4) + w;      // g*128 + j*16 + w
    const long out_base = ((long)g * rows) * OUT_COLS4 + c4;

    const float4* ip = in  + (long)row0 * IN_COLS4 + in_col4;
    float4*       op = out + out_base + (long)row0 * OUT_COLS4;

    if (row0 + 28 < rows) {
        // fast path: 8 independent loads issued before any store
        float4 v0 = __ldcs(ip);
        float4 v1 = __ldcs(ip + 4L  * IN_COLS4);
        float4 v2 = __ldcs(ip + 8L  * IN_COLS4);
        float4 v3 = __ldcs(ip + 12L * IN_COLS4);
        float4 v4 = __ldcs(ip + 16L * IN_COLS4);
        float4 v5 = __ldcs(ip + 20L * IN_COLS4);
        float4 v6 = __ldcs(ip + 24L * IN_COLS4);
        float4 v7 = __ldcs(ip + 28L * IN_COLS4);
        __stcs(op,                   v0);
        __stcs(op + 4L  * OUT_COLS4, v1);
        __stcs(op + 8L  * OUT_COLS4, v2);
        __stcs(op + 12L * OUT_COLS4, v3);
        __stcs(op + 16L * OUT_COLS4, v4);
        __stcs(op + 20L * OUT_COLS4, v5);
        __stcs(op + 24L * OUT_COLS4, v6);
        __stcs(op + 28L * OUT_COLS4, v7);
    } else {
#pragma unroll
        for (int k = 0; k < 8; ++k) {
            const int row = row0 + (k << 2);
            if (row < rows)
                __stcs(op + (long)(k << 2) * OUT_COLS4,
                       __ldcs(ip + (long)(k << 2) * IN_COLS4));
        }
    }
}

extern "C" void kernel_launch(void* const* d_in, const int* in_sizes, int n_in,
                              void* d_out, int out_size)
{
    const float4* in  = (const float4*)d_in[0];
    float4*       out = (float4*)d_out;

    const int rows = in_sizes[0] / 4096;     // 16384 reference

    dim3 block(256, 1, 1);
    dim3 grid((rows + ROWS_PER_BLK - 1) / ROWS_PER_BLK, 1, 8);  // (512, 1, 8)
    slice_cat_kernel<<<grid, block>>>(in, out, rows);
}